// round 13
// baseline (speedup 1.0000x reference)
#include <cuda_runtime.h>
#include <cuda_bf16.h>
#include <cuda_fp16.h>
#include <cstdint>

#define NMAX 100000
#define CC   128
#define EMAX 1600000
#define SCAN_B 1024

// ---------------- scratch (static device globals; no allocation) -------------
__device__ __half g_h [(size_t)NMAX * CC];    // post-GEMM features (fp16)
__device__ float g_agg [(size_t)NMAX * CC];
__device__ float g_dinv[NMAX];
__device__ int   g_deg [NMAX];
__device__ int   g_rowstart[NMAX + 1];
__device__ int   g_cursor[NMAX];
__device__ int   g_srcidx[EMAX];
__device__ float g_enorm [EMAX];
__device__ int   g_part[256];
__device__ int   g_partbase[256];
__device__ float g_sum[CC], g_sumsq[CC], g_scale[CC], g_shift[CC];
// pre-packed bf16 B fragments: [layer][kt 4][s2 2][n8 16][lane 32] {bh0,bh1,bl0,bl1}
__device__ uint4 g_Bfrag[2][4][2][16][32];

// ---------------- helpers -----------------------------------------------------
__device__ __forceinline__ uint32_t pack_bf16(float x, float y) {
    uint32_t d;
    asm("cvt.rn.bf16x2.f32 %0, %1, %2;" : "=r"(d) : "f"(y), "f"(x));
    return d;
}
__device__ __forceinline__ uint32_t pack_bf16_res(float x, float y, uint32_t p) {
    float hx = __uint_as_float(p << 16);
    float hy = __uint_as_float(p & 0xffff0000u);
    uint32_t d;
    asm("cvt.rn.bf16x2.f32 %0, %1, %2;" : "=r"(d) : "f"(y - hy), "f"(x - hx));
    return d;
}

__device__ __forceinline__ void mma_bf16(float* c, const uint32_t* a, uint32_t b0, uint32_t b1) {
    asm volatile(
        "mma.sync.aligned.m16n8k16.row.col.f32.bf16.bf16.f32 "
        "{%0,%1,%2,%3},{%4,%5,%6,%7},{%8,%9},{%0,%1,%2,%3};"
        : "+f"(c[0]), "+f"(c[1]), "+f"(c[2]), "+f"(c[3])
        : "r"(a[0]), "r"(a[1]), "r"(a[2]), "r"(a[3]), "r"(b0), "r"(b1));
}

// load 4 channels (lane*4..+3) of fp16 row v as float4
__device__ __forceinline__ float4 ldh4(const __half* __restrict__ H, int v, int lane) {
    uint2 u = *((const uint2*)(H + ((size_t)v << 7)) + lane);
    __half2 a = *reinterpret_cast<__half2*>(&u.x);
    __half2 b = *reinterpret_cast<__half2*>(&u.y);
    float2 f0 = __half22float2(a), f1 = __half22float2(b);
    return make_float4(f0.x, f0.y, f1.x, f1.y);
}

// ---------------- setup kernels ----------------------------------------------
__global__ void k_setup0(int n, const float* __restrict__ W1,
                         const float* __restrict__ W2) {
    int i = blockIdx.x * blockDim.x + threadIdx.x;
    if (i < n) g_deg[i] = 0;
    if (i < 8192) {
        int lane = i & 31;
        int rest = i >> 5;
        int n8   = rest & 15;
        int s2   = (rest >> 4) & 1;
        int ktI  = (rest >> 5) & 3;
        int layer = rest >> 7;
        const float* W = layer ? W2 : W1;
        int g = lane >> 2, tg = lane & 3;
        int kk = ktI * 32 + s2 * 16;
        int nn = n8 * 8 + g;
        float b00 = W[(kk + 2 * tg)     * 128 + nn];
        float b01 = W[(kk + 2 * tg + 1) * 128 + nn];
        float b10 = W[(kk + 2 * tg + 8) * 128 + nn];
        float b11 = W[(kk + 2 * tg + 9) * 128 + nn];
        uint4 o;
        o.x = pack_bf16(b00, b01);
        o.y = pack_bf16(b10, b11);
        o.z = pack_bf16_res(b00, b01, o.x);
        o.w = pack_bf16_res(b10, b11, o.y);
        g_Bfrag[layer][ktI][s2][n8][lane] = o;
    }
}

__global__ void k_count(const int* __restrict__ ei, int E) {
    int e = blockIdx.x * blockDim.x + threadIdx.x;
    if (e >= E) return;
    atomicAdd(&g_deg[ei[E + e]], 1);
}

__global__ __launch_bounds__(SCAN_B) void k_scan1(int n) {
    __shared__ int s[SCAN_B];
    int t = threadIdx.x;
    int i = blockIdx.x * SCAN_B + t;
    int v = (i < n) ? g_deg[i] : 0;
    if (i < n) g_dinv[i] = rsqrtf((float)v + 1.0f);
    s[t] = v;
    __syncthreads();
#pragma unroll
    for (int off = 1; off < SCAN_B; off <<= 1) {
        int add = (t >= off) ? s[t - off] : 0;
        __syncthreads();
        s[t] += add;
        __syncthreads();
    }
    if (i < n) g_rowstart[i] = s[t] - v;
    if (t == SCAN_B - 1) g_part[blockIdx.x] = s[t];
}

__global__ void k_scan2(int nb, int n) {
    __shared__ int s[256];
    int t = threadIdx.x;
    if (t < CC) { g_sum[t] = 0.f; g_sumsq[t] = 0.f; }
    int v = (t < nb) ? g_part[t] : 0;
    s[t] = v;
    __syncthreads();
#pragma unroll
    for (int off = 1; off < 256; off <<= 1) {
        int add = (t >= off) ? s[t - off] : 0;
        __syncthreads();
        s[t] += add;
        __syncthreads();
    }
    if (t < nb) g_partbase[t] = s[t] - v;
    if (t == 255) g_rowstart[n] = s[255];
}

__global__ __launch_bounds__(SCAN_B) void k_scan3(int n) {
    int i = blockIdx.x * SCAN_B + threadIdx.x;
    if (i >= n) return;
    int r = g_rowstart[i] + g_partbase[blockIdx.x];
    g_rowstart[i] = r;
    g_cursor[i]   = r;
}

__global__ void k_fill(const int* __restrict__ ei, int E) {
    int e = blockIdx.x * blockDim.x + threadIdx.x;
    if (e >= E) return;
    int sN = ei[e];
    int d  = ei[E + e];
    int p = atomicAdd(&g_cursor[d], 1);
    g_srcidx[p] = sN;
    g_enorm[p]  = g_dinv[sN] * g_dinv[d];
}

// ---------------- bf16 tensor-core GEMM: H = X @ W  (H stored fp16) ----------
// 3-pass compensated bf16 via mma.sync m16n8k16.
// A staged per-K-chunk in FRAGMENT ORDER: AF[((wm*2+s2)*2+mi)*128 + lane*4 + j]
// -> consumption is one conflict-free LDS.128 per (mi, hi/lo).
// B fragment table (64KB) staged once into SMEM. Next A chunk prefetched into
// registers during MMAs; 2 CTAs/SM.
#define AFRAG_WORDS (16 * 128)                 // 4 wm x 2 s2 x 2 mi x 128
#define A_BYTES (2 * AFRAG_WORDS * 4)          // Ah+Al = 16384 B
#define SMEM_GEMM (A_BYTES + 4096 * 16)        // + B table 65536 B = 81920 B
template <bool BN_FUSE>
__global__ __launch_bounds__(256, 2) void k_gemm_bf16(const float* __restrict__ X,
                                                      const uint4* __restrict__ Bf,
                                                      __half* __restrict__ H, int n) {
    extern __shared__ char sm[];
    uint32_t* AhF = (uint32_t*)sm;
    uint32_t* AlF = AhF + AFRAG_WORDS;
    uint4*    Bs  = (uint4*)(sm + A_BYTES);

    int tid = threadIdx.x;
    int wid = tid >> 5, lane = tid & 31;
    int wm = wid & 3, wn = wid >> 2;        // warp grid 4x2
    int g = lane >> 2, tg = lane & 3;
    int br = blockIdx.x * 128;

    // stage B fragment table (4096 uint4)
#pragma unroll
    for (int i = 0; i < 16; i++) Bs[tid + i * 256] = Bf[tid + i * 256];

    // staging decomposition: this thread handles rows arow+32*i (i = wm of row),
    // k-pair indices 2*akc and 2*akc+1.
    int arow = tid >> 3;                    // 0..31
    int akc  = tid & 7;                     // float4 index within 32-k chunk
    int smi = (arow >> 4) & 1;              // mi of staged rows
    int sb  = (arow >> 3) & 1;              // b of staged rows
    int sg  = arow & 7;                     // g of staged rows
    int ss2 = akc >> 2;                     // s2 of both k-pairs
    int stg0 = 2 * (akc & 1);               // tg of first k-pair
    int sc0  = (akc >> 1) & 1;              // c of both k-pairs
    // frag slot for h0; h1 is +4 (tg+1)
    int sbase = (ss2 * 2 + smi) * 128 + (sg * 4 + stg0) * 4 + sb + 2 * sc0;

    const float* aptr = X + (size_t)(br + arow) * 128 + akc * 4;

    float acc[2][8][4];
#pragma unroll
    for (int mi = 0; mi < 2; mi++)
#pragma unroll
        for (int nj = 0; nj < 8; nj++)
#pragma unroll
            for (int j = 0; j < 4; j++) acc[mi][nj][j] = 0.f;

    // prefetch chunk 0 (rows arow, +32, +64, +96)
    float4 va[4];
#pragma unroll
    for (int i = 0; i < 4; i++) {
        va[i] = make_float4(0.f, 0.f, 0.f, 0.f);
        if (br + arow + i * 32 < n)
            va[i] = *(const float4*)(aptr + (size_t)(i * 32) * 128);
    }

    for (int ktI = 0; ktI < 4; ktI++) {
        // transform + store staged chunk to smem (fragment order; i == wm)
#pragma unroll
        for (int i = 0; i < 4; i++) {
            float4 v = va[i];
            if (BN_FUSE) {
                int f4 = ktI * 8 + akc;
                float4 sc = ((const float4*)g_scale)[f4];
                float4 sh = ((const float4*)g_shift)[f4];
                v.x = fmaxf(fmaf(v.x, sc.x, sh.x), 0.f);
                v.y = fmaxf(fmaf(v.y, sc.y, sh.y), 0.f);
                v.z = fmaxf(fmaf(v.z, sc.z, sh.z), 0.f);
                v.w = fmaxf(fmaf(v.w, sc.w, sh.w), 0.f);
            }
            int base = i * 4 * 128 + sbase;
            uint32_t h0 = pack_bf16(v.x, v.y);
            uint32_t h1 = pack_bf16(v.z, v.w);
            AhF[base]     = h0;
            AhF[base + 4] = h1;
            AlF[base]     = pack_bf16_res(v.x, v.y, h0);
            AlF[base + 4] = pack_bf16_res(v.z, v.w, h1);
        }
        __syncthreads();

        // prefetch next chunk while MMAs run
        if (ktI < 3) {
            const float* np = aptr + (ktI + 1) * 32;
#pragma unroll
            for (int i = 0; i < 4; i++) {
                va[i] = make_float4(0.f, 0.f, 0.f, 0.f);
                if (br + arow + i * 32 < n)
                    va[i] = *(const float4*)(np + (size_t)(i * 32) * 128);
            }
        }

#pragma unroll
        for (int s2 = 0; s2 < 2; s2++) {
            // A fragments: one LDS.128 each (conflict-free)
            uint4 ah4[2], al4[2];
#pragma unroll
            for (int mi = 0; mi < 2; mi++) {
                int fb = ((wm * 2 + s2) * 2 + mi) * 128 + lane * 4;
                ah4[mi] = *(const uint4*)(AhF + fb);
                al4[mi] = *(const uint4*)(AlF + fb);
            }
            const uint4* bp = Bs + (((ktI * 2 + s2) * 16 + wn * 8) * 32 + lane);
#pragma unroll
            for (int nj = 0; nj < 8; nj++) {
                uint4 bf = bp[nj * 32];
#pragma unroll
                for (int mi = 0; mi < 2; mi++) {
                    mma_bf16(acc[mi][nj], (const uint32_t*)&ah4[mi], bf.x, bf.y);
                    mma_bf16(acc[mi][nj], (const uint32_t*)&al4[mi], bf.x, bf.y);
                    mma_bf16(acc[mi][nj], (const uint32_t*)&ah4[mi], bf.z, bf.w);
                }
            }
        }
        __syncthreads();
    }

    // epilogue -> fp16 H
#pragma unroll
    for (int mi = 0; mi < 2; mi++) {
        int row = br + wm * 32 + mi * 16 + g;
#pragma unroll
        for (int nj = 0; nj < 8; nj++) {
            int col = wn * 64 + nj * 8 + 2 * tg;
            if (row < n)
                *(__half2*)(H + ((size_t)row << 7) + col) =
                    __floats2half2_rn(acc[mi][nj][0], acc[mi][nj][1]);
            if (row + 8 < n)
                *(__half2*)(H + ((size_t)(row + 8) << 7) + col) =
                    __floats2half2_rn(acc[mi][nj][2], acc[mi][nj][3]);
        }
    }
}

// ---------------- CSR gather aggregation + fused BN stats (fp16 H) ------------
__global__ __launch_bounds__(256) void k_agg_stats(const __half* __restrict__ H,
                                                   const float* __restrict__ b,
                                                   float* __restrict__ AGG, int n) {
    __shared__ float ssum[8][128];
    __shared__ float ssq [8][128];
    int wid = threadIdx.x >> 5;
    int lane = threadIdx.x & 31;
    int v = blockIdx.x * 8 + wid;

    float4 acc = make_float4(0.f, 0.f, 0.f, 0.f);
    if (v < n) {
        float dinv = g_dinv[v];
        float self = dinv * dinv;
        float4 hv = ldh4(H, v, lane);
        float4 bv = *(const float4*)(b + lane * 4);
        acc.x = hv.x * self + bv.x;
        acc.y = hv.y * self + bv.y;
        acc.z = hv.z * self + bv.z;
        acc.w = hv.w * self + bv.w;

        int rs = g_rowstart[v], re = g_rowstart[v + 1];
        int e = rs;
        for (; e + 4 <= re; e += 4) {
            int s0 = g_srcidx[e],     s1 = g_srcidx[e + 1];
            int s2 = g_srcidx[e + 2], s3 = g_srcidx[e + 3];
            float n0 = g_enorm[e],     n1 = g_enorm[e + 1];
            float n2 = g_enorm[e + 2], n3 = g_enorm[e + 3];
            float4 h0 = ldh4(H, s0, lane);
            float4 h1 = ldh4(H, s1, lane);
            float4 h2 = ldh4(H, s2, lane);
            float4 h3 = ldh4(H, s3, lane);
            acc.x += h0.x * n0 + h1.x * n1 + h2.x * n2 + h3.x * n3;
            acc.y += h0.y * n0 + h1.y * n1 + h2.y * n2 + h3.y * n3;
            acc.z += h0.z * n0 + h1.z * n1 + h2.z * n2 + h3.z * n3;
            acc.w += h0.w * n0 + h1.w * n1 + h2.w * n2 + h3.w * n3;
        }
        for (; e < re; e++) {
            int s0 = g_srcidx[e];
            float n0 = g_enorm[e];
            float4 h0 = ldh4(H, s0, lane);
            acc.x += h0.x * n0;
            acc.y += h0.y * n0;
            acc.z += h0.z * n0;
            acc.w += h0.w * n0;
        }
        *(float4*)(AGG + (size_t)v * 128 + lane * 4) = acc;
    }

    float4 q;
    q.x = acc.x * acc.x; q.y = acc.y * acc.y;
    q.z = acc.z * acc.z; q.w = acc.w * acc.w;
    *(float4*)&ssum[wid][lane * 4] = acc;
    *(float4*)&ssq [wid][lane * 4] = q;
    __syncthreads();
    int t = threadIdx.x;
    if (t < 128) {
        float s = 0.f, qq = 0.f;
#pragma unroll
        for (int r = 0; r < 8; r++) { s += ssum[r][t]; qq += ssq[r][t]; }
        atomicAdd(&g_sum[t], s);
        atomicAdd(&g_sumsq[t], qq);
    }
}

// ---------------- batchnorm finalize (+ re-zero stats) ------------------------
__global__ void k_bn_final(const float* __restrict__ gamma,
                           const float* __restrict__ beta, int n) {
    int c = threadIdx.x;
    float invn = 1.0f / (float)n;
    float m = g_sum[c] * invn;
    float var = g_sumsq[c] * invn - m * m;
    float rstd = rsqrtf(var + 1e-5f);
    float sc = gamma[c] * rstd;
    g_scale[c] = sc;
    g_shift[c] = beta[c] - m * sc;
    g_sum[c] = 0.f;
    g_sumsq[c] = 0.f;
}

__global__ void k_apply_relu_res(const float* __restrict__ A,
                                 const float* __restrict__ X,
                                 float* __restrict__ O, int total4) {
    int i = blockIdx.x * blockDim.x + threadIdx.x;
    if (i >= total4) return;
    int c4 = i & 31;
    float4 sc = ((const float4*)g_scale)[c4];
    float4 sh = ((const float4*)g_shift)[c4];
    float4 a = ((const float4*)A)[i];
    float4 x = ((const float4*)X)[i];
    float4 o;
    o.x = fmaxf(fmaf(a.x, sc.x, sh.x) + x.x, 0.f);
    o.y = fmaxf(fmaf(a.y, sc.y, sh.y) + x.y, 0.f);
    o.z = fmaxf(fmaf(a.z, sc.z, sh.z) + x.z, 0.f);
    o.w = fmaxf(fmaf(a.w, sc.w, sh.w) + x.w, 0.f);
    ((float4*)O)[i] = o;
}

// ---------------- launch ------------------------------------------------------
extern "C" void kernel_launch(void* const* d_in, const int* in_sizes, int n_in,
                              void* d_out, int out_size) {
    const float* x     = (const float*)d_in[0];
    const float* W1    = (const float*)d_in[1];
    const float* b1    = (const float*)d_in[2];
    const float* W2    = (const float*)d_in[3];
    const float* b2    = (const float*)d_in[4];
    const float* gamma = (const float*)d_in[5];
    const float* beta  = (const float*)d_in[6];
    const int*   ei    = (const int*)d_in[7];   // int32 [2, E]

    int n = in_sizes[0] / CC;
    int E = in_sizes[7] / 2;
    float* out = (float*)d_out;

    __half* p_h;
    float*  p_agg;
    uint4*  p_bfrag;
    cudaGetSymbolAddress((void**)&p_h,     g_h);
    cudaGetSymbolAddress((void**)&p_agg,   g_agg);
    cudaGetSymbolAddress((void**)&p_bfrag, g_Bfrag);
    const uint4* bf1 = p_bfrag;
    const uint4* bf2 = p_bfrag + 4 * 2 * 16 * 32;

    cudaFuncSetAttribute(k_gemm_bf16<false>, cudaFuncAttributeMaxDynamicSharedMemorySize, SMEM_GEMM);
    cudaFuncSetAttribute(k_gemm_bf16<true>,  cudaFuncAttributeMaxDynamicSharedMemorySize, SMEM_GEMM);

    int nb_n  = (n + 255) / 256;
    int nb_e  = (E + 255) / 256;
    int nb_sc = (n + SCAN_B - 1) / SCAN_B;
    int total4 = n * (CC / 4);
    int nb_4  = (total4 + 255) / 256;
    int nb_gemm = (n + 127) / 128;
    int nb_agg  = (n + 7) / 8;

    // launch order: layer-1 GEMM at index 3 (ncu capture slot)
    k_setup0<<<nb_n, 256>>>(n, W1, W2);                               // 0
    k_count<<<nb_e, 256>>>(ei, E);                                    // 1
    k_scan1<<<nb_sc, SCAN_B>>>(n);                                    // 2
    k_gemm_bf16<false><<<nb_gemm, 256, SMEM_GEMM>>>(x, bf1, p_h, n);  // 3 <- profiled
    k_scan2<<<1, 256>>>(nb_sc, n);                                    // 4  (zeros stats)
    k_scan3<<<nb_sc, SCAN_B>>>(n);                                    // 5
    k_fill<<<nb_e, 256>>>(ei, E);                                     // 6

    // --- layer 1 ---
    k_agg_stats<<<nb_agg, 256>>>(p_h, b1, p_agg, n);                  // 7
    k_bn_final<<<1, 128>>>(gamma, beta, n);                           // 8

    // --- layer 2 ---
    k_gemm_bf16<true><<<nb_gemm, 256, SMEM_GEMM>>>(p_agg, bf2, p_h, n); // 9
    k_agg_stats<<<nb_agg, 256>>>(p_h, b2, p_agg, n);                  // 10
    k_bn_final<<<1, 128>>>(gamma, beta, n);                           // 11
    k_apply_relu_res<<<nb_4, 256>>>(p_agg, x, out, total4);           // 12
}

// round 16
// speedup vs baseline: 1.4481x; 1.4481x over previous
#include <cuda_runtime.h>
#include <cuda_bf16.h>
#include <cuda_fp16.h>
#include <cstdint>

#define NMAX 100000
#define CC   128
#define EMAX 1600000
#define SCAN_B 1024

// ---------------- scratch (static device globals; no allocation) -------------
__device__ __half g_h [(size_t)NMAX * CC];    // post-GEMM features (fp16)
__device__ float g_agg [(size_t)NMAX * CC];
__device__ float g_dinv[NMAX];
__device__ int   g_deg [NMAX];
__device__ int   g_rowstart[NMAX + 1];
__device__ int   g_cursor[NMAX];
__device__ int   g_srcidx[EMAX];
__device__ float g_enorm [EMAX];
__device__ int   g_part[256];
__device__ int   g_partbase[256];
__device__ float g_sum[CC], g_sumsq[CC], g_scale[CC], g_shift[CC];
// pre-packed bf16 B fragments: [layer][kt 4][s2 2][n8 16][lane 32] {bh0,bh1,bl0,bl1}
__device__ uint4 g_Bfrag[2][4][2][16][32];

// ---------------- helpers -----------------------------------------------------
__device__ __forceinline__ uint32_t pack_bf16(float x, float y) {
    uint32_t d;
    asm("cvt.rn.bf16x2.f32 %0, %1, %2;" : "=r"(d) : "f"(y), "f"(x));
    return d;
}
__device__ __forceinline__ uint32_t pack_bf16_res(float x, float y, uint32_t p) {
    float hx = __uint_as_float(p << 16);
    float hy = __uint_as_float(p & 0xffff0000u);
    uint32_t d;
    asm("cvt.rn.bf16x2.f32 %0, %1, %2;" : "=r"(d) : "f"(y - hy), "f"(x - hx));
    return d;
}

__device__ __forceinline__ void mma_bf16(float* c, const uint32_t* a, uint32_t b0, uint32_t b1) {
    asm volatile(
        "mma.sync.aligned.m16n8k16.row.col.f32.bf16.bf16.f32 "
        "{%0,%1,%2,%3},{%4,%5,%6,%7},{%8,%9},{%0,%1,%2,%3};"
        : "+f"(c[0]), "+f"(c[1]), "+f"(c[2]), "+f"(c[3])
        : "r"(a[0]), "r"(a[1]), "r"(a[2]), "r"(a[3]), "r"(b0), "r"(b1));
}

// load 4 channels (lane*4..+3) of fp16 row v as float4
__device__ __forceinline__ float4 ldh4(const __half* __restrict__ H, int v, int lane) {
    uint2 u = *((const uint2*)(H + ((size_t)v << 7)) + lane);
    __half2 a = *reinterpret_cast<__half2*>(&u.x);
    __half2 b = *reinterpret_cast<__half2*>(&u.y);
    float2 f0 = __half22float2(a), f1 = __half22float2(b);
    return make_float4(f0.x, f0.y, f1.x, f1.y);
}

// ---------------- setup kernels ----------------------------------------------
__global__ void k_setup0(int n, const float* __restrict__ W1,
                         const float* __restrict__ W2) {
    int i = blockIdx.x * blockDim.x + threadIdx.x;
    if (i < n) g_deg[i] = 0;
    if (i < 8192) {
        int lane = i & 31;
        int rest = i >> 5;
        int n8   = rest & 15;
        int s2   = (rest >> 4) & 1;
        int ktI  = (rest >> 5) & 3;
        int layer = rest >> 7;
        const float* W = layer ? W2 : W1;
        int g = lane >> 2, tg = lane & 3;
        int kk = ktI * 32 + s2 * 16;
        int nn = n8 * 8 + g;
        float b00 = W[(kk + 2 * tg)     * 128 + nn];
        float b01 = W[(kk + 2 * tg + 1) * 128 + nn];
        float b10 = W[(kk + 2 * tg + 8) * 128 + nn];
        float b11 = W[(kk + 2 * tg + 9) * 128 + nn];
        uint4 o;
        o.x = pack_bf16(b00, b01);
        o.y = pack_bf16(b10, b11);
        o.z = pack_bf16_res(b00, b01, o.x);
        o.w = pack_bf16_res(b10, b11, o.y);
        g_Bfrag[layer][ktI][s2][n8][lane] = o;
    }
}

__global__ void k_count(const int* __restrict__ ei, int E) {
    int e = blockIdx.x * blockDim.x + threadIdx.x;
    if (e >= E) return;
    atomicAdd(&g_deg[ei[E + e]], 1);
}

__global__ __launch_bounds__(SCAN_B) void k_scan1(int n) {
    __shared__ int s[SCAN_B];
    int t = threadIdx.x;
    int i = blockIdx.x * SCAN_B + t;
    int v = (i < n) ? g_deg[i] : 0;
    if (i < n) g_dinv[i] = rsqrtf((float)v + 1.0f);
    s[t] = v;
    __syncthreads();
#pragma unroll
    for (int off = 1; off < SCAN_B; off <<= 1) {
        int add = (t >= off) ? s[t - off] : 0;
        __syncthreads();
        s[t] += add;
        __syncthreads();
    }
    if (i < n) g_rowstart[i] = s[t] - v;
    if (t == SCAN_B - 1) g_part[blockIdx.x] = s[t];
}

__global__ void k_scan2(int nb, int n) {
    __shared__ int s[256];
    int t = threadIdx.x;
    if (t < CC) { g_sum[t] = 0.f; g_sumsq[t] = 0.f; }
    int v = (t < nb) ? g_part[t] : 0;
    s[t] = v;
    __syncthreads();
#pragma unroll
    for (int off = 1; off < 256; off <<= 1) {
        int add = (t >= off) ? s[t - off] : 0;
        __syncthreads();
        s[t] += add;
        __syncthreads();
    }
    if (t < nb) g_partbase[t] = s[t] - v;
    if (t == 255) g_rowstart[n] = s[255];
}

__global__ __launch_bounds__(SCAN_B) void k_scan3(int n) {
    int i = blockIdx.x * SCAN_B + threadIdx.x;
    if (i >= n) return;
    int r = g_rowstart[i] + g_partbase[blockIdx.x];
    g_rowstart[i] = r;
    g_cursor[i]   = r;
}

__global__ void k_fill(const int* __restrict__ ei, int E) {
    int e = blockIdx.x * blockDim.x + threadIdx.x;
    if (e >= E) return;
    int sN = ei[e];
    int d  = ei[E + e];
    int p = atomicAdd(&g_cursor[d], 1);
    g_srcidx[p] = sN;
    g_enorm[p]  = g_dinv[sN] * g_dinv[d];
}

// ---------------- bf16 tensor-core GEMM: H = X @ W  (H stored fp16) ----------
// 3-pass compensated bf16 via mma.sync m16n8k16.
// A staged per-K-chunk in FRAGMENT ORDER: AF[((wm*2+s2)*2+mi)*128 + lane*4 + j]
// -> consumption is one conflict-free LDS.128 per (mi, hi/lo).
// B fragment table (64KB) staged once into SMEM. Next A chunk prefetched into
// registers during MMAs; 2 CTAs/SM.
#define AFRAG_WORDS (16 * 128)                 // 4 wm x 2 s2 x 2 mi x 128
#define A_BYTES (2 * AFRAG_WORDS * 4)          // Ah+Al = 16384 B
#define SMEM_GEMM (A_BYTES + 4096 * 16)        // + B table 65536 B = 81920 B
template <bool BN_FUSE>
__global__ __launch_bounds__(256, 2) void k_gemm_bf16(const float* __restrict__ X,
                                                      const uint4* __restrict__ Bf,
                                                      __half* __restrict__ H, int n) {
    extern __shared__ char sm[];
    uint32_t* AhF = (uint32_t*)sm;
    uint32_t* AlF = AhF + AFRAG_WORDS;
    uint4*    Bs  = (uint4*)(sm + A_BYTES);

    int tid = threadIdx.x;
    int wid = tid >> 5, lane = tid & 31;
    int wm = wid & 3, wn = wid >> 2;        // warp grid 4x2
    int g = lane >> 2, tg = lane & 3;
    int br = blockIdx.x * 128;

    // stage B fragment table (4096 uint4)
#pragma unroll
    for (int i = 0; i < 16; i++) Bs[tid + i * 256] = Bf[tid + i * 256];

    // staging decomposition: rows arow+32*i (i == wm of row), k-pairs 2*akc, 2*akc+1
    int arow = tid >> 3;                    // 0..31
    int akc  = tid & 7;
    int smi = (arow >> 4) & 1;
    int sb  = (arow >> 3) & 1;
    int sg  = arow & 7;
    int ss2 = akc >> 2;
    int stg0 = 2 * (akc & 1);
    int sc0  = (akc >> 1) & 1;
    int sbase = (ss2 * 2 + smi) * 128 + (sg * 4 + stg0) * 4 + sb + 2 * sc0;

    const float* aptr = X + (size_t)(br + arow) * 128 + akc * 4;

    float acc[2][8][4];
#pragma unroll
    for (int mi = 0; mi < 2; mi++)
#pragma unroll
        for (int nj = 0; nj < 8; nj++)
#pragma unroll
            for (int j = 0; j < 4; j++) acc[mi][nj][j] = 0.f;

    // prefetch chunk 0 (rows arow, +32, +64, +96)
    float4 va[4];
#pragma unroll
    for (int i = 0; i < 4; i++) {
        va[i] = make_float4(0.f, 0.f, 0.f, 0.f);
        if (br + arow + i * 32 < n)
            va[i] = *(const float4*)(aptr + (size_t)(i * 32) * 128);
    }

    for (int ktI = 0; ktI < 4; ktI++) {
        // transform + store staged chunk to smem (fragment order; i == wm)
#pragma unroll
        for (int i = 0; i < 4; i++) {
            float4 v = va[i];
            if (BN_FUSE) {
                int f4 = ktI * 8 + akc;
                float4 sc = ((const float4*)g_scale)[f4];
                float4 sh = ((const float4*)g_shift)[f4];
                v.x = fmaxf(fmaf(v.x, sc.x, sh.x), 0.f);
                v.y = fmaxf(fmaf(v.y, sc.y, sh.y), 0.f);
                v.z = fmaxf(fmaf(v.z, sc.z, sh.z), 0.f);
                v.w = fmaxf(fmaf(v.w, sc.w, sh.w), 0.f);
            }
            int base = i * 4 * 128 + sbase;
            uint32_t h0 = pack_bf16(v.x, v.y);
            uint32_t h1 = pack_bf16(v.z, v.w);
            AhF[base]     = h0;
            AhF[base + 4] = h1;
            AlF[base]     = pack_bf16_res(v.x, v.y, h0);
            AlF[base + 4] = pack_bf16_res(v.z, v.w, h1);
        }
        __syncthreads();

        // prefetch next chunk while MMAs run
        if (ktI < 3) {
            const float* np = aptr + (ktI + 1) * 32;
#pragma unroll
            for (int i = 0; i < 4; i++) {
                va[i] = make_float4(0.f, 0.f, 0.f, 0.f);
                if (br + arow + i * 32 < n)
                    va[i] = *(const float4*)(np + (size_t)(i * 32) * 128);
            }
        }

#pragma unroll
        for (int s2 = 0; s2 < 2; s2++) {
            uint4 ah4[2], al4[2];
#pragma unroll
            for (int mi = 0; mi < 2; mi++) {
                int fb = ((wm * 2 + s2) * 2 + mi) * 128 + lane * 4;
                ah4[mi] = *(const uint4*)(AhF + fb);
                al4[mi] = *(const uint4*)(AlF + fb);
            }
            const uint4* bp = Bs + (((ktI * 2 + s2) * 16 + wn * 8) * 32 + lane);
#pragma unroll
            for (int nj = 0; nj < 8; nj++) {
                uint4 bf = bp[nj * 32];
#pragma unroll
                for (int mi = 0; mi < 2; mi++) {
                    mma_bf16(acc[mi][nj], (const uint32_t*)&ah4[mi], bf.x, bf.y);
                    mma_bf16(acc[mi][nj], (const uint32_t*)&al4[mi], bf.x, bf.y);
                    mma_bf16(acc[mi][nj], (const uint32_t*)&ah4[mi], bf.z, bf.w);
                }
            }
        }
        __syncthreads();
    }

    // epilogue -> fp16 H
#pragma unroll
    for (int mi = 0; mi < 2; mi++) {
        int row = br + wm * 32 + mi * 16 + g;
#pragma unroll
        for (int nj = 0; nj < 8; nj++) {
            int col = wn * 64 + nj * 8 + 2 * tg;
            if (row < n)
                *(__half2*)(H + ((size_t)row << 7) + col) =
                    __floats2half2_rn(acc[mi][nj][0], acc[mi][nj][1]);
            if (row + 8 < n)
                *(__half2*)(H + ((size_t)(row + 8) << 7) + col) =
                    __floats2half2_rn(acc[mi][nj][2], acc[mi][nj][3]);
        }
    }
}

// ---------------- per-node CSR gather aggregation (fp16 H) --------------------
__global__ __launch_bounds__(256) void k_agg(const __half* __restrict__ H,
                                             const float* __restrict__ b,
                                             float* __restrict__ AGG, int n) {
    int warp = (blockIdx.x * blockDim.x + threadIdx.x) >> 5;
    int lane = threadIdx.x & 31;
    if (warp >= n) return;
    int v = warp;
    float dinv = g_dinv[v];
    float self = dinv * dinv;
    float4 hv = ldh4(H, v, lane);
    float4 bv = *(const float4*)(b + lane * 4);
    float4 acc;
    acc.x = hv.x * self + bv.x;
    acc.y = hv.y * self + bv.y;
    acc.z = hv.z * self + bv.z;
    acc.w = hv.w * self + bv.w;

    int rs = g_rowstart[v], re = g_rowstart[v + 1];
    int e = rs;
    for (; e + 4 <= re; e += 4) {
        int s0 = g_srcidx[e],     s1 = g_srcidx[e + 1];
        int s2 = g_srcidx[e + 2], s3 = g_srcidx[e + 3];
        float n0 = g_enorm[e],     n1 = g_enorm[e + 1];
        float n2 = g_enorm[e + 2], n3 = g_enorm[e + 3];
        float4 h0 = ldh4(H, s0, lane);
        float4 h1 = ldh4(H, s1, lane);
        float4 h2 = ldh4(H, s2, lane);
        float4 h3 = ldh4(H, s3, lane);
        acc.x += h0.x * n0 + h1.x * n1 + h2.x * n2 + h3.x * n3;
        acc.y += h0.y * n0 + h1.y * n1 + h2.y * n2 + h3.y * n3;
        acc.z += h0.z * n0 + h1.z * n1 + h2.z * n2 + h3.z * n3;
        acc.w += h0.w * n0 + h1.w * n1 + h2.w * n2 + h3.w * n3;
    }
    for (; e < re; e++) {
        int s0 = g_srcidx[e];
        float n0 = g_enorm[e];
        float4 h0 = ldh4(H, s0, lane);
        acc.x += h0.x * n0;
        acc.y += h0.y * n0;
        acc.z += h0.z * n0;
        acc.w += h0.w * n0;
    }
    *(float4*)(AGG + (size_t)v * 128 + lane * 4) = acc;
}

// ---------------- batchnorm ---------------------------------------------------
__global__ __launch_bounds__(128) void k_stats(const float* __restrict__ A, int n) {
    int c = threadIdx.x;
    int nb = gridDim.x;
    int chunk = (n + nb - 1) / nb;
    int r0 = blockIdx.x * chunk;
    int r1 = min(n, r0 + chunk);
    float s = 0.f, sq = 0.f;
    for (int r = r0; r < r1; r++) {
        float v = A[(size_t)r * 128 + c];
        s += v;
        sq += v * v;
    }
    atomicAdd(&g_sum[c], s);
    atomicAdd(&g_sumsq[c], sq);
}

__global__ void k_bn_final(const float* __restrict__ gamma,
                           const float* __restrict__ beta, int n) {
    int c = threadIdx.x;
    float invn = 1.0f / (float)n;
    float m = g_sum[c] * invn;
    float var = g_sumsq[c] * invn - m * m;
    float rstd = rsqrtf(var + 1e-5f);
    float sc = gamma[c] * rstd;
    g_scale[c] = sc;
    g_shift[c] = beta[c] - m * sc;
    g_sum[c] = 0.f;
    g_sumsq[c] = 0.f;
}

__global__ void k_apply_relu_res(const float* __restrict__ A,
                                 const float* __restrict__ X,
                                 float* __restrict__ O, int total4) {
    int i = blockIdx.x * blockDim.x + threadIdx.x;
    if (i >= total4) return;
    int c4 = i & 31;
    float4 sc = ((const float4*)g_scale)[c4];
    float4 sh = ((const float4*)g_shift)[c4];
    float4 a = ((const float4*)A)[i];
    float4 x = ((const float4*)X)[i];
    float4 o;
    o.x = fmaxf(fmaf(a.x, sc.x, sh.x) + x.x, 0.f);
    o.y = fmaxf(fmaf(a.y, sc.y, sh.y) + x.y, 0.f);
    o.z = fmaxf(fmaf(a.z, sc.z, sh.z) + x.z, 0.f);
    o.w = fmaxf(fmaf(a.w, sc.w, sh.w) + x.w, 0.f);
    ((float4*)O)[i] = o;
}

// ---------------- launch ------------------------------------------------------
extern "C" void kernel_launch(void* const* d_in, const int* in_sizes, int n_in,
                              void* d_out, int out_size) {
    const float* x     = (const float*)d_in[0];
    const float* W1    = (const float*)d_in[1];
    const float* b1    = (const float*)d_in[2];
    const float* W2    = (const float*)d_in[3];
    const float* b2    = (const float*)d_in[4];
    const float* gamma = (const float*)d_in[5];
    const float* beta  = (const float*)d_in[6];
    const int*   ei    = (const int*)d_in[7];   // int32 [2, E]

    int n = in_sizes[0] / CC;
    int E = in_sizes[7] / 2;
    float* out = (float*)d_out;

    __half* p_h;
    float*  p_agg;
    uint4*  p_bfrag;
    cudaGetSymbolAddress((void**)&p_h,     g_h);
    cudaGetSymbolAddress((void**)&p_agg,   g_agg);
    cudaGetSymbolAddress((void**)&p_bfrag, g_Bfrag);
    const uint4* bf1 = p_bfrag;
    const uint4* bf2 = p_bfrag + 4 * 2 * 16 * 32;

    cudaFuncSetAttribute(k_gemm_bf16<false>, cudaFuncAttributeMaxDynamicSharedMemorySize, SMEM_GEMM);
    cudaFuncSetAttribute(k_gemm_bf16<true>,  cudaFuncAttributeMaxDynamicSharedMemorySize, SMEM_GEMM);

    int nb_n  = (n + 255) / 256;
    int nb_e  = (E + 255) / 256;
    int nb_sc = (n + SCAN_B - 1) / SCAN_B;
    int total4 = n * (CC / 4);
    int nb_4  = (total4 + 255) / 256;
    int nb_gemm = (n + 127) / 128;
    int nb_ew = (n * 32 + 255) / 256;   // warp-per-node agg

    // launch order: layer-1 GEMM at index 3 (ncu capture slot)
    k_setup0<<<nb_n, 256>>>(n, W1, W2);                               // 0
    k_count<<<nb_e, 256>>>(ei, E);                                    // 1
    k_scan1<<<nb_sc, SCAN_B>>>(n);                                    // 2
    k_gemm_bf16<false><<<nb_gemm, 256, SMEM_GEMM>>>(x, bf1, p_h, n);  // 3 <- profiled
    k_scan2<<<1, 256>>>(nb_sc, n);                                    // 4  (zeros stats)
    k_scan3<<<nb_sc, SCAN_B>>>(n);                                    // 5
    k_fill<<<nb_e, 256>>>(ei, E);                                     // 6

    // --- layer 1 ---
    k_agg<<<nb_ew, 256>>>(p_h, b1, p_agg, n);                         // 7
    k_stats<<<512, 128>>>(p_agg, n);                                  // 8
    k_bn_final<<<1, 128>>>(gamma, beta, n);                           // 9

    // --- layer 2 ---
    k_gemm_bf16<true><<<nb_gemm, 256, SMEM_GEMM>>>(p_agg, bf2, p_h, n); // 10
    k_agg<<<nb_ew, 256>>>(p_h, b2, p_agg, n);                         // 11
    k_stats<<<512, 128>>>(p_agg, n);                                  // 12
    k_bn_final<<<1, 128>>>(gamma, beta, n);                           // 13
    k_apply_relu_res<<<nb_4, 256>>>(p_agg, x, out, total4);           // 14
}